// round 1
// baseline (speedup 1.0000x reference)
#include <cuda_runtime.h>
#include <math.h>

#define BATCH 4
#define SLEN 2048
#define DDIM 1024
#define NHEAD 16
#define DKH 64
#define MROWS (BATCH * SLEN)  // 8192

// Scratch (alloc-free rule: __device__ globals)
__device__ float g_Q[MROWS * DDIM];
__device__ float g_K[MROWS * DDIM];
__device__ float g_V[MROWS * DDIM];
__device__ float g_A[MROWS * DDIM];

// ======================= GEMM: Y = X @ W^T =======================
// X: [M, K] row-major, W: [N, K] row-major (torch Linear weight), Y: [M, N]
#define GBM 128
#define GBN 128
#define GBK 16
#define GTM 8
#define GTN 8

__device__ __forceinline__ void sgemm_nt(const float* __restrict__ X,
                                         const float* __restrict__ W,
                                         float* __restrict__ Y) {
    __shared__ float As[GBK][GBM];
    __shared__ float Bs[GBK][GBN];
    const int bm = blockIdx.y * GBM;
    const int bn = blockIdx.x * GBN;
    const int tid = threadIdx.x;
    const int tr = tid >> 4;   // 0..15
    const int tc = tid & 15;   // 0..15

    float acc[GTM][GTN];
#pragma unroll
    for (int i = 0; i < GTM; i++)
#pragma unroll
        for (int j = 0; j < GTN; j++) acc[i][j] = 0.f;

    for (int k0 = 0; k0 < DDIM; k0 += GBK) {
        // Load 128x16 tiles of X and W (transposed into [k][m] layout in smem)
#pragma unroll
        for (int t = 0; t < 2; t++) {
            int idx = tid + t * 256;
            int row = idx >> 2;          // 0..127
            int c4  = (idx & 3) * 4;     // 0,4,8,12
            float4 va = *(const float4*)(X + (size_t)(bm + row) * DDIM + k0 + c4);
            As[c4 + 0][row] = va.x;
            As[c4 + 1][row] = va.y;
            As[c4 + 2][row] = va.z;
            As[c4 + 3][row] = va.w;
            float4 vb = *(const float4*)(W + (size_t)(bn + row) * DDIM + k0 + c4);
            Bs[c4 + 0][row] = vb.x;
            Bs[c4 + 1][row] = vb.y;
            Bs[c4 + 2][row] = vb.z;
            Bs[c4 + 3][row] = vb.w;
        }
        __syncthreads();
#pragma unroll
        for (int k = 0; k < GBK; k++) {
            float ra[GTM], rb[GTN];
            *(float4*)&ra[0] = *(const float4*)&As[k][tr * GTM];
            *(float4*)&ra[4] = *(const float4*)&As[k][tr * GTM + 4];
            *(float4*)&rb[0] = *(const float4*)&Bs[k][tc * GTN];
            *(float4*)&rb[4] = *(const float4*)&Bs[k][tc * GTN + 4];
#pragma unroll
            for (int i = 0; i < GTM; i++)
#pragma unroll
                for (int j = 0; j < GTN; j++) acc[i][j] += ra[i] * rb[j];
        }
        __syncthreads();
    }
#pragma unroll
    for (int i = 0; i < GTM; i++) {
        float* yp = Y + (size_t)(bm + tr * GTM + i) * DDIM + bn + tc * GTN;
        *(float4*)(yp)     = make_float4(acc[i][0], acc[i][1], acc[i][2], acc[i][3]);
        *(float4*)(yp + 4) = make_float4(acc[i][4], acc[i][5], acc[i][6], acc[i][7]);
    }
}

__global__ __launch_bounds__(256) void qkv_kernel(const float* __restrict__ X,
                                                  const float* __restrict__ Wq,
                                                  const float* __restrict__ Wk,
                                                  const float* __restrict__ Wv) {
    const float* W = (blockIdx.z == 0) ? Wq : (blockIdx.z == 1) ? Wk : Wv;
    float* Y = (blockIdx.z == 0) ? g_Q : (blockIdx.z == 1) ? g_K : g_V;
    sgemm_nt(X, W, Y);
}

__global__ __launch_bounds__(256) void oproj_kernel(const float* __restrict__ Wo,
                                                    float* __restrict__ out) {
    sgemm_nt(g_A, Wo, out);
}

// ======================= Flash attention (fp32) =======================
// Per block: one (b, h), 128 query rows. Stream over 64-row K/V tiles with
// online softmax. Thread grid 16x16; each thread owns an 8x4 micro-tile.
#define ABQ 128
#define ABK 64
#define ATM 8
#define ATN 4

__global__ __launch_bounds__(256, 2) void attn_kernel() {
    extern __shared__ float smf[];
    float* Qs = smf;                        // [128][64]
    float* Ks = Qs + ABQ * DKH;             // [64][65]  (pad to break bank conflicts)
    float* Vs = Ks + ABK * (DKH + 1);       // [64][64]
    float* Ps = Vs + ABK * DKH;             // [128][65]

    const int tid = threadIdx.x;
    const int ty = tid >> 4;   // 0..15 (owns rows ty*8 .. ty*8+7)
    const int tx = tid & 15;   // 0..15 (owns cols tx*4 .. tx*4+3)
    const int b  = blockIdx.y >> 4;
    const int h  = blockIdx.y & 15;
    const int q0 = blockIdx.x * ABQ;
    const size_t base = (size_t)b * SLEN * DDIM + (size_t)h * DKH;
    const float* Qg = g_Q + base;
    const float* Kg = g_K + base;
    const float* Vg = g_V + base;

    // Load Q tile [128][64]
    for (int i = tid; i < ABQ * (DKH / 4); i += 256) {
        int r = i >> 4;
        int c = (i & 15) * 4;
        *(float4*)(Qs + r * DKH + c) =
            *(const float4*)(Qg + (size_t)(q0 + r) * DDIM + c);
    }

    float m[ATM], l[ATM], o[ATM][ATN];
#pragma unroll
    for (int i = 0; i < ATM; i++) {
        m[i] = -1e30f;
        l[i] = 0.f;
#pragma unroll
        for (int j = 0; j < ATN; j++) o[i][j] = 0.f;
    }
    const float scale = 0.125f;  // 1/sqrt(64)

    for (int k0 = 0; k0 < SLEN; k0 += ABK) {
        __syncthreads();  // previous iteration's reads of Ks/Vs/Ps complete
        // Load K and V tiles [64][64]
        for (int i = tid; i < ABK * (DKH / 4); i += 256) {
            int r = i >> 4;
            int c = (i & 15) * 4;
            float4 kv = *(const float4*)(Kg + (size_t)(k0 + r) * DDIM + c);
            Ks[r * (DKH + 1) + c + 0] = kv.x;
            Ks[r * (DKH + 1) + c + 1] = kv.y;
            Ks[r * (DKH + 1) + c + 2] = kv.z;
            Ks[r * (DKH + 1) + c + 3] = kv.w;
            *(float4*)(Vs + r * DKH + c) =
                *(const float4*)(Vg + (size_t)(k0 + r) * DDIM + c);
        }
        __syncthreads();

        // S = (Q K^T): 128x64 tile, 8x4 per thread
        float s[ATM][ATN];
#pragma unroll
        for (int i = 0; i < ATM; i++)
#pragma unroll
            for (int j = 0; j < ATN; j++) s[i][j] = 0.f;
#pragma unroll 4
        for (int kk = 0; kk < ABK; kk++) {
            float a[ATM], bb[ATN];
#pragma unroll
            for (int i = 0; i < ATM; i++) a[i] = Qs[(ty * ATM + i) * DKH + kk];
#pragma unroll
            for (int j = 0; j < ATN; j++) bb[j] = Ks[(tx * ATN + j) * (DKH + 1) + kk];
#pragma unroll
            for (int i = 0; i < ATM; i++)
#pragma unroll
                for (int j = 0; j < ATN; j++) s[i][j] += a[i] * bb[j];
        }

        // Online softmax update (per-row stats replicated across the 16 tx lanes)
#pragma unroll
        for (int i = 0; i < ATM; i++) {
#pragma unroll
            for (int j = 0; j < ATN; j++) s[i][j] *= scale;
            float rm = fmaxf(fmaxf(s[i][0], s[i][1]), fmaxf(s[i][2], s[i][3]));
#pragma unroll
            for (int off = 8; off >= 1; off >>= 1)
                rm = fmaxf(rm, __shfl_xor_sync(0xffffffffu, rm, off));
            float mn = fmaxf(m[i], rm);
            float al = __expf(m[i] - mn);
            float rs = 0.f;
#pragma unroll
            for (int j = 0; j < ATN; j++) {
                float p = __expf(s[i][j] - mn);
                s[i][j] = p;
                rs += p;
            }
#pragma unroll
            for (int off = 8; off >= 1; off >>= 1)
                rs += __shfl_xor_sync(0xffffffffu, rs, off);
            l[i] = l[i] * al + rs;
            m[i] = mn;
#pragma unroll
            for (int j = 0; j < ATN; j++) o[i][j] *= al;
        }

        // Stage P tile into smem for the PV GEMM
#pragma unroll
        for (int i = 0; i < ATM; i++)
#pragma unroll
            for (int j = 0; j < ATN; j++)
                Ps[(ty * ATM + i) * (ABK + 1) + tx * ATN + j] = s[i][j];
        __syncthreads();

        // O += P @ V
#pragma unroll 4
        for (int kk = 0; kk < ABK; kk++) {
            float a[ATM];
#pragma unroll
            for (int i = 0; i < ATM; i++) a[i] = Ps[(ty * ATM + i) * (ABK + 1) + kk];
            float4 bv = *(const float4*)(Vs + kk * DKH + tx * ATN);
#pragma unroll
            for (int i = 0; i < ATM; i++) {
                o[i][0] += a[i] * bv.x;
                o[i][1] += a[i] * bv.y;
                o[i][2] += a[i] * bv.z;
                o[i][3] += a[i] * bv.w;
            }
        }
    }

    // Epilogue: normalize and write to g_A in [B, S, D] layout
    float* Og = g_A + base;
#pragma unroll
    for (int i = 0; i < ATM; i++) {
        float inv = 1.f / l[i];
        *(float4*)(Og + (size_t)(q0 + ty * ATM + i) * DDIM + tx * ATN) =
            make_float4(o[i][0] * inv, o[i][1] * inv, o[i][2] * inv, o[i][3] * inv);
    }
}

// ======================= launch =======================
extern "C" void kernel_launch(void* const* d_in, const int* in_sizes, int n_in,
                              void* d_out, int out_size) {
    const float* emb = (const float*)d_in[0];
    const float* Wq  = (const float*)d_in[1];
    const float* Wk  = (const float*)d_in[2];
    const float* Wv  = (const float*)d_in[3];
    const float* Wo  = (const float*)d_in[4];
    float* out = (float*)d_out;

    // Q/K/V projections: one launch, z selects the weight
    dim3 ggrid(DDIM / GBN, MROWS / GBM, 3);
    qkv_kernel<<<ggrid, 256>>>(emb, Wq, Wk, Wv);

    // Attention
    const int smem_bytes =
        (ABQ * DKH + ABK * (DKH + 1) + ABK * DKH + ABQ * (ABK + 1)) * (int)sizeof(float);
    cudaFuncSetAttribute(attn_kernel, cudaFuncAttributeMaxDynamicSharedMemorySize,
                         smem_bytes);
    dim3 agrid(SLEN / ABQ, BATCH * NHEAD);
    attn_kernel<<<agrid, 256, smem_bytes>>>();

    // Output projection
    dim3 ogrid(DDIM / GBN, MROWS / GBM, 1);
    oproj_kernel<<<ogrid, 256>>>(Wo, out);
}

// round 3
// speedup vs baseline: 1.4162x; 1.4162x over previous
#include <cuda_runtime.h>
#include <cuda_bf16.h>
#include <stdint.h>
#include <math.h>

#define BATCH 4
#define SLEN 2048
#define DDIM 1024
#define NHEAD 16
#define DKH 64
#define MROWS (BATCH * SLEN)  // 8192

// Scratch (alloc-free rule: __device__ globals)
__device__ float g_Q[MROWS * DDIM];
__device__ float g_K[MROWS * DDIM];
__device__ float g_V[MROWS * DDIM];
__device__ float g_A[MROWS * DDIM];

// ===================== mma.sync helpers (arch-agnostic tensor path) =====================
// m16n8k16 row.col bf16 -> f32.  D += A*B.
__device__ __forceinline__ void mma16816(float* c, const uint32_t* a, const uint32_t* b) {
    asm volatile(
        "mma.sync.aligned.m16n8k16.row.col.f32.bf16.bf16.f32 "
        "{%0,%1,%2,%3}, {%4,%5,%6,%7}, {%8,%9}, {%0,%1,%2,%3};"
        : "+f"(c[0]), "+f"(c[1]), "+f"(c[2]), "+f"(c[3])
        : "r"(a[0]), "r"(a[1]), "r"(a[2]), "r"(a[3]), "r"(b[0]), "r"(b[1]));
}

// fp32 -> (bf16 hi, bf16 lo) split of a float4, packed as bf16x2 pairs in k-order.
__device__ __forceinline__ void split4(float4 v, uint2& hi, uint2& lo) {
    __nv_bfloat16 h0 = __float2bfloat16_rn(v.x);
    __nv_bfloat16 h1 = __float2bfloat16_rn(v.y);
    __nv_bfloat16 h2 = __float2bfloat16_rn(v.z);
    __nv_bfloat16 h3 = __float2bfloat16_rn(v.w);
    __nv_bfloat16 l0 = __float2bfloat16_rn(v.x - __bfloat162float(h0));
    __nv_bfloat16 l1 = __float2bfloat16_rn(v.y - __bfloat162float(h1));
    __nv_bfloat16 l2 = __float2bfloat16_rn(v.z - __bfloat162float(h2));
    __nv_bfloat16 l3 = __float2bfloat16_rn(v.w - __bfloat162float(h3));
    __nv_bfloat162 t;
    t.x = h0; t.y = h1; hi.x = *reinterpret_cast<uint32_t*>(&t);
    t.x = h2; t.y = h3; hi.y = *reinterpret_cast<uint32_t*>(&t);
    t.x = l0; t.y = l1; lo.x = *reinterpret_cast<uint32_t*>(&t);
    t.x = l2; t.y = l3; lo.y = *reinterpret_cast<uint32_t*>(&t);
}

// ===================== GEMM: Y = X @ W^T  (mma.sync bf16, 3-term split) =====================
// X: [M,K] row-major fp32, W: [N,K] row-major fp32 (torch Linear), Y: [M,N] fp32.
// CTA: 128x128 tile, 8 warps (2x4), warp tile 64x32. K in 32-elem stages, double buffered.
#define KC 32
#define NS (DDIM / KC)              // 32 stages
#define TSTR 40                     // smem row stride in bf16 elems (80B; conflict-free quads)
#define TILE_HALF (128 * TSTR)      // one hi or lo tile, in elems
#define BUF_ELEMS (4 * TILE_HALF)   // Ah, Al, Bh, Bl
#define GEMM_SMEM (2 * BUF_ELEMS * 2)  // bytes: double buffer

__device__ __forceinline__ void mma_gemm(const float* __restrict__ X,
                                         const float* __restrict__ W,
                                         float* __restrict__ Y) {
    extern __shared__ char smem_raw[];
    __nv_bfloat16* smem = (__nv_bfloat16*)smem_raw;

    const int tid = threadIdx.x;
    const int warp = tid >> 5, lane = tid & 31;
    const int wm = warp >> 2;      // 0..1  -> m offset wm*64
    const int wn = warp & 3;       // 0..3  -> n offset wn*32
    const int g = lane >> 2;       // group row 0..7
    const int tq = lane & 3;       // quad lane
    const int bm = blockIdx.y * 128;
    const int bn = blockIdx.x * 128;

    float acc[4][4][4];
#pragma unroll
    for (int i = 0; i < 4; i++)
#pragma unroll
        for (int j = 0; j < 4; j++)
#pragma unroll
            for (int r = 0; r < 4; r++) acc[i][j][r] = 0.f;

    float4 xr[4], wr[4];

    auto ldg_stage = [&](int s) {
        const int k0 = s * KC;
#pragma unroll
        for (int it = 0; it < 4; it++) {
            int idx = tid + it * 256;
            int row = idx >> 3;
            int c4 = (idx & 7) << 2;
            xr[it] = *(const float4*)(X + (size_t)(bm + row) * DDIM + k0 + c4);
            wr[it] = *(const float4*)(W + (size_t)(bn + row) * DDIM + k0 + c4);
        }
    };

    auto sts_stage = [&](int b) {
        __nv_bfloat16* Ah = smem + b * BUF_ELEMS;
        __nv_bfloat16* Al = Ah + TILE_HALF;
        __nv_bfloat16* Bh = Ah + 2 * TILE_HALF;
        __nv_bfloat16* Bl = Ah + 3 * TILE_HALF;
#pragma unroll
        for (int it = 0; it < 4; it++) {
            int idx = tid + it * 256;
            int row = idx >> 3;
            int c4 = (idx & 7) << 2;
            int off = row * TSTR + c4;
            uint2 hi, lo;
            split4(xr[it], hi, lo);
            *(uint2*)(Ah + off) = hi;
            *(uint2*)(Al + off) = lo;
            split4(wr[it], hi, lo);
            *(uint2*)(Bh + off) = hi;
            *(uint2*)(Bl + off) = lo;
        }
    };

    auto compute = [&](int b) {
        const __nv_bfloat16* Ah = smem + b * BUF_ELEMS;
        const __nv_bfloat16* Al = Ah + TILE_HALF;
        const __nv_bfloat16* Bh = Ah + 2 * TILE_HALF;
        const __nv_bfloat16* Bl = Ah + 3 * TILE_HALF;
#pragma unroll
        for (int kk = 0; kk < 2; kk++) {
            const int kb = kk * 16 + tq * 2;
            uint32_t ah[4][4], al[4][4], bh[4][2], bl[4][2];
#pragma unroll
            for (int mt = 0; mt < 4; mt++) {
                const int r0 = wm * 64 + mt * 16 + g;
                ah[mt][0] = *(const uint32_t*)(Ah + r0 * TSTR + kb);
                ah[mt][1] = *(const uint32_t*)(Ah + (r0 + 8) * TSTR + kb);
                ah[mt][2] = *(const uint32_t*)(Ah + r0 * TSTR + kb + 8);
                ah[mt][3] = *(const uint32_t*)(Ah + (r0 + 8) * TSTR + kb + 8);
                al[mt][0] = *(const uint32_t*)(Al + r0 * TSTR + kb);
                al[mt][1] = *(const uint32_t*)(Al + (r0 + 8) * TSTR + kb);
                al[mt][2] = *(const uint32_t*)(Al + r0 * TSTR + kb + 8);
                al[mt][3] = *(const uint32_t*)(Al + (r0 + 8) * TSTR + kb + 8);
            }
#pragma unroll
            for (int nt = 0; nt < 4; nt++) {
                const int n0 = wn * 32 + nt * 8 + g;
                bh[nt][0] = *(const uint32_t*)(Bh + n0 * TSTR + kb);
                bh[nt][1] = *(const uint32_t*)(Bh + n0 * TSTR + kb + 8);
                bl[nt][0] = *(const uint32_t*)(Bl + n0 * TSTR + kb);
                bl[nt][1] = *(const uint32_t*)(Bl + n0 * TSTR + kb + 8);
            }
#pragma unroll
            for (int mt = 0; mt < 4; mt++)
#pragma unroll
                for (int nt = 0; nt < 4; nt++) {
                    mma16816(acc[mt][nt], ah[mt], bh[nt]);
                    mma16816(acc[mt][nt], ah[mt], bl[nt]);
                    mma16816(acc[mt][nt], al[mt], bh[nt]);
                }
        }
    };

    ldg_stage(0);
    sts_stage(0);
    __syncthreads();

    for (int s = 0; s < NS; s++) {
        if (s + 1 < NS) ldg_stage(s + 1);
        compute(s & 1);
        if (s + 1 < NS) sts_stage((s + 1) & 1);
        __syncthreads();
    }

    // Epilogue: direct stores (8B pairs, coalesced within quads)
#pragma unroll
    for (int mt = 0; mt < 4; mt++) {
        const int row = bm + wm * 64 + mt * 16 + g;
#pragma unroll
        for (int nt = 0; nt < 4; nt++) {
            const int col = bn + wn * 32 + nt * 8 + tq * 2;
            *(float2*)(Y + (size_t)row * DDIM + col) =
                make_float2(acc[mt][nt][0], acc[mt][nt][1]);
            *(float2*)(Y + (size_t)(row + 8) * DDIM + col) =
                make_float2(acc[mt][nt][2], acc[mt][nt][3]);
        }
    }
}

__global__ __launch_bounds__(256, 1) void qkv_mma(const float* __restrict__ X,
                                                  const float* __restrict__ Wq,
                                                  const float* __restrict__ Wk,
                                                  const float* __restrict__ Wv) {
    const float* W = (blockIdx.z == 0) ? Wq : (blockIdx.z == 1) ? Wk : Wv;
    float* Y = (blockIdx.z == 0) ? g_Q : (blockIdx.z == 1) ? g_K : g_V;
    mma_gemm(X, W, Y);
}

__global__ __launch_bounds__(256, 1) void oproj_mma(const float* __restrict__ Wo,
                                                    float* __restrict__ out) {
    mma_gemm(g_A, Wo, out);
}

// ============== Flash attention (fp32) — unchanged from round 1 (passing) ==============
#define ABQ 128
#define ABK 64
#define ATM 8
#define ATN 4

__global__ __launch_bounds__(256, 2) void attn_kernel() {
    extern __shared__ char smem_raw[];
    float* smf = (float*)smem_raw;
    float* Qs = smf;
    float* Ks = Qs + ABQ * DKH;
    float* Vs = Ks + ABK * (DKH + 1);
    float* Ps = Vs + ABK * DKH;

    const int tid = threadIdx.x;
    const int ty = tid >> 4;
    const int tx = tid & 15;
    const int b  = blockIdx.y >> 4;
    const int h  = blockIdx.y & 15;
    const int q0 = blockIdx.x * ABQ;
    const size_t base = (size_t)b * SLEN * DDIM + (size_t)h * DKH;
    const float* Qg = g_Q + base;
    const float* Kg = g_K + base;
    const float* Vg = g_V + base;

    for (int i = tid; i < ABQ * (DKH / 4); i += 256) {
        int r = i >> 4;
        int c = (i & 15) * 4;
        *(float4*)(Qs + r * DKH + c) =
            *(const float4*)(Qg + (size_t)(q0 + r) * DDIM + c);
    }

    float m[ATM], l[ATM], o[ATM][ATN];
#pragma unroll
    for (int i = 0; i < ATM; i++) {
        m[i] = -1e30f;
        l[i] = 0.f;
#pragma unroll
        for (int j = 0; j < ATN; j++) o[i][j] = 0.f;
    }
    const float scale = 0.125f;

    for (int k0 = 0; k0 < SLEN; k0 += ABK) {
        __syncthreads();
        for (int i = tid; i < ABK * (DKH / 4); i += 256) {
            int r = i >> 4;
            int c = (i & 15) * 4;
            float4 kv = *(const float4*)(Kg + (size_t)(k0 + r) * DDIM + c);
            Ks[r * (DKH + 1) + c + 0] = kv.x;
            Ks[r * (DKH + 1) + c + 1] = kv.y;
            Ks[r * (DKH + 1) + c + 2] = kv.z;
            Ks[r * (DKH + 1) + c + 3] = kv.w;
            *(float4*)(Vs + r * DKH + c) =
                *(const float4*)(Vg + (size_t)(k0 + r) * DDIM + c);
        }
        __syncthreads();

        float s[ATM][ATN];
#pragma unroll
        for (int i = 0; i < ATM; i++)
#pragma unroll
            for (int j = 0; j < ATN; j++) s[i][j] = 0.f;
#pragma unroll 4
        for (int kk = 0; kk < ABK; kk++) {
            float a[ATM], bb[ATN];
#pragma unroll
            for (int i = 0; i < ATM; i++) a[i] = Qs[(ty * ATM + i) * DKH + kk];
#pragma unroll
            for (int j = 0; j < ATN; j++) bb[j] = Ks[(tx * ATN + j) * (DKH + 1) + kk];
#pragma unroll
            for (int i = 0; i < ATM; i++)
#pragma unroll
                for (int j = 0; j < ATN; j++) s[i][j] += a[i] * bb[j];
        }

#pragma unroll
        for (int i = 0; i < ATM; i++) {
#pragma unroll
            for (int j = 0; j < ATN; j++) s[i][j] *= scale;
            float rm = fmaxf(fmaxf(s[i][0], s[i][1]), fmaxf(s[i][2], s[i][3]));
#pragma unroll
            for (int off = 8; off >= 1; off >>= 1)
                rm = fmaxf(rm, __shfl_xor_sync(0xffffffffu, rm, off));
            float mn = fmaxf(m[i], rm);
            float al = __expf(m[i] - mn);
            float rs = 0.f;
#pragma unroll
            for (int j = 0; j < ATN; j++) {
                float p = __expf(s[i][j] - mn);
                s[i][j] = p;
                rs += p;
            }
#pragma unroll
            for (int off = 8; off >= 1; off >>= 1)
                rs += __shfl_xor_sync(0xffffffffu, rs, off);
            l[i] = l[i] * al + rs;
            m[i] = mn;
#pragma unroll
            for (int j = 0; j < ATN; j++) o[i][j] *= al;
        }

#pragma unroll
        for (int i = 0; i < ATM; i++)
#pragma unroll
            for (int j = 0; j < ATN; j++)
                Ps[(ty * ATM + i) * (ABK + 1) + tx * ATN + j] = s[i][j];
        __syncthreads();

#pragma unroll 4
        for (int kk = 0; kk < ABK; kk++) {
            float a[ATM];
#pragma unroll
            for (int i = 0; i < ATM; i++) a[i] = Ps[(ty * ATM + i) * (ABK + 1) + kk];
            float4 bv = *(const float4*)(Vs + kk * DKH + tx * ATN);
#pragma unroll
            for (int i = 0; i < ATM; i++) {
                o[i][0] += a[i] * bv.x;
                o[i][1] += a[i] * bv.y;
                o[i][2] += a[i] * bv.z;
                o[i][3] += a[i] * bv.w;
            }
        }
    }

    float* Og = g_A + base;
#pragma unroll
    for (int i = 0; i < ATM; i++) {
        float inv = 1.f / l[i];
        *(float4*)(Og + (size_t)(q0 + ty * ATM + i) * DDIM + tx * ATN) =
            make_float4(o[i][0] * inv, o[i][1] * inv, o[i][2] * inv, o[i][3] * inv);
    }
}

// ======================= launch =======================
extern "C" void kernel_launch(void* const* d_in, const int* in_sizes, int n_in,
                              void* d_out, int out_size) {
    const float* emb = (const float*)d_in[0];
    const float* Wq  = (const float*)d_in[1];
    const float* Wk  = (const float*)d_in[2];
    const float* Wv  = (const float*)d_in[3];
    const float* Wo  = (const float*)d_in[4];
    float* out = (float*)d_out;

    cudaFuncSetAttribute(qkv_mma, cudaFuncAttributeMaxDynamicSharedMemorySize, GEMM_SMEM);
    cudaFuncSetAttribute(oproj_mma, cudaFuncAttributeMaxDynamicSharedMemorySize, GEMM_SMEM);

    dim3 ggrid(DDIM / 128, MROWS / 128, 3);
    qkv_mma<<<ggrid, 256, GEMM_SMEM>>>(emb, Wq, Wk, Wv);

    const int attn_smem =
        (ABQ * DKH + ABK * (DKH + 1) + ABK * DKH + ABQ * (ABK + 1)) * (int)sizeof(float);
    cudaFuncSetAttribute(attn_kernel, cudaFuncAttributeMaxDynamicSharedMemorySize,
                         attn_smem);
    dim3 agrid(SLEN / ABQ, BATCH * NHEAD);
    attn_kernel<<<agrid, 256, attn_smem>>>();

    dim3 ogrid(DDIM / 128, MROWS / 128, 1);
    oproj_mma<<<ogrid, 256, GEMM_SMEM>>>(Wo, out);
}

// round 4
// speedup vs baseline: 2.3770x; 1.6785x over previous
#include <cuda_runtime.h>
#include <cuda_bf16.h>
#include <stdint.h>
#include <math.h>

#define BATCH 4
#define SLEN 2048
#define DDIM 1024
#define NHEAD 16
#define DKH 64
#define MROWS (BATCH * SLEN)  // 8192

// Scratch (alloc-free rule: __device__ globals)
__device__ __nv_bfloat16 g_Qh[MROWS * DDIM];
__device__ __nv_bfloat16 g_Ql[MROWS * DDIM];
__device__ __nv_bfloat16 g_Kh[MROWS * DDIM];
__device__ __nv_bfloat16 g_Kl[MROWS * DDIM];
__device__ __nv_bfloat16 g_Vh[MROWS * DDIM];
__device__ __nv_bfloat16 g_Vl[MROWS * DDIM];
__device__ float g_A[MROWS * DDIM];

// ===================== common helpers =====================
__device__ __forceinline__ uint32_t smem_u32(const void* p) {
    uint32_t a;
    asm("{ .reg .u64 t; cvta.to.shared.u64 t, %1; cvt.u32.u64 %0, t; }"
        : "=r"(a) : "l"(p));
    return a;
}

// m16n8k16 row.col bf16 -> f32.  D += A*B.
__device__ __forceinline__ void mma16816(float* c, const uint32_t* a, const uint32_t* b) {
    asm volatile(
        "mma.sync.aligned.m16n8k16.row.col.f32.bf16.bf16.f32 "
        "{%0,%1,%2,%3}, {%4,%5,%6,%7}, {%8,%9}, {%0,%1,%2,%3};"
        : "+f"(c[0]), "+f"(c[1]), "+f"(c[2]), "+f"(c[3])
        : "r"(a[0]), "r"(a[1]), "r"(a[2]), "r"(a[3]), "r"(b[0]), "r"(b[1]));
}

// pack two f32 -> bf16x2 (x -> low half, y -> high half)
__device__ __forceinline__ uint32_t packbf(float x, float y) {
    uint32_t r;
    asm("cvt.rn.bf16x2.f32 %0, %1, %2;" : "=r"(r) : "f"(y), "f"(x));
    return r;
}
__device__ __forceinline__ void unpackbf(uint32_t w, float& x, float& y) {
    x = __int_as_float(w << 16);
    y = __int_as_float(w & 0xffff0000u);
}

__device__ __forceinline__ void split4(float4 v, uint2& hi, uint2& lo) {
    uint32_t h0 = packbf(v.x, v.y), h1 = packbf(v.z, v.w);
    float a, b, c, d;
    unpackbf(h0, a, b);
    unpackbf(h1, c, d);
    hi.x = h0; hi.y = h1;
    lo.x = packbf(v.x - a, v.y - b);
    lo.y = packbf(v.z - c, v.w - d);
}

// fast exp2 on fma/alu pipes (input <= 0); rel err ~2e-7
__device__ __forceinline__ float fexp2(float t) {
    t = fmaxf(t, -125.f);
    float fi = floorf(t);
    float f = t - fi;
    float p = 1.5353362e-4f;
    p = fmaf(p, f, 1.3398874e-3f);
    p = fmaf(p, f, 9.6184374e-3f);
    p = fmaf(p, f, 5.5503325e-2f);
    p = fmaf(p, f, 2.4022648e-1f);
    p = fmaf(p, f, 6.9314720e-1f);
    p = fmaf(p, f, 1.0f);
    return __int_as_float(__float_as_int(p) + ((int)fi << 23));
}

#define LDSM4(r0, r1, r2, r3, addr)                                            \
    asm volatile("ldmatrix.sync.aligned.m8n8.x4.shared.b16 {%0,%1,%2,%3}, [%4];" \
                 : "=r"(r0), "=r"(r1), "=r"(r2), "=r"(r3) : "r"(addr))
#define LDSM4T(r0, r1, r2, r3, addr)                                           \
    asm volatile("ldmatrix.sync.aligned.m8n8.x4.trans.shared.b16 {%0,%1,%2,%3}, [%4];" \
                 : "=r"(r0), "=r"(r1), "=r"(r2), "=r"(r3) : "r"(addr))

#define CP16(dst, src) \
    asm volatile("cp.async.cg.shared.global [%0], [%1], 16;" :: "r"(dst), "l"(src))
#define CP_COMMIT() asm volatile("cp.async.commit_group;")
#define CP_WAIT(n) asm volatile("cp.async.wait_group %0;" :: "n"(n))

// ===================== GEMM: Y = X @ W^T  (mma.sync bf16, 3-term split) =====================
#define KC 32
#define NS (DDIM / KC)
#define TSTR 40
#define TILE_HALF (128 * TSTR)
#define BUF_ELEMS (4 * TILE_HALF)
#define GEMM_SMEM (2 * BUF_ELEMS * 2)

template <bool SPLIT_OUT>
__device__ __forceinline__ void mma_gemm(const float* __restrict__ X,
                                         const float* __restrict__ W,
                                         float* __restrict__ Yf,
                                         __nv_bfloat16* __restrict__ Yh,
                                         __nv_bfloat16* __restrict__ Yl) {
    extern __shared__ char smem_raw[];
    __nv_bfloat16* smem = (__nv_bfloat16*)smem_raw;

    const int tid = threadIdx.x;
    const int warp = tid >> 5, lane = tid & 31;
    const int wm = warp >> 2;
    const int wn = warp & 3;
    const int g = lane >> 2;
    const int tq = lane & 3;
    const int bm = blockIdx.y * 128;
    const int bn = blockIdx.x * 128;

    float acc[4][4][4];
#pragma unroll
    for (int i = 0; i < 4; i++)
#pragma unroll
        for (int j = 0; j < 4; j++)
#pragma unroll
            for (int r = 0; r < 4; r++) acc[i][j][r] = 0.f;

    float4 xr[4], wr[4];

    auto ldg_stage = [&](int s) {
        const int k0 = s * KC;
#pragma unroll
        for (int it = 0; it < 4; it++) {
            int idx = tid + it * 256;
            int row = idx >> 3;
            int c4 = (idx & 7) << 2;
            xr[it] = *(const float4*)(X + (size_t)(bm + row) * DDIM + k0 + c4);
            wr[it] = *(const float4*)(W + (size_t)(bn + row) * DDIM + k0 + c4);
        }
    };

    auto sts_stage = [&](int b) {
        __nv_bfloat16* Ah = smem + b * BUF_ELEMS;
        __nv_bfloat16* Al = Ah + TILE_HALF;
        __nv_bfloat16* Bh = Ah + 2 * TILE_HALF;
        __nv_bfloat16* Bl = Ah + 3 * TILE_HALF;
#pragma unroll
        for (int it = 0; it < 4; it++) {
            int idx = tid + it * 256;
            int row = idx >> 3;
            int c4 = (idx & 7) << 2;
            int off = row * TSTR + c4;
            uint2 hi, lo;
            split4(xr[it], hi, lo);
            *(uint2*)(Ah + off) = hi;
            *(uint2*)(Al + off) = lo;
            split4(wr[it], hi, lo);
            *(uint2*)(Bh + off) = hi;
            *(uint2*)(Bl + off) = lo;
        }
    };

    auto compute = [&](int b) {
        const __nv_bfloat16* Ah = smem + b * BUF_ELEMS;
        const __nv_bfloat16* Al = Ah + TILE_HALF;
        const __nv_bfloat16* Bh = Ah + 2 * TILE_HALF;
        const __nv_bfloat16* Bl = Ah + 3 * TILE_HALF;
#pragma unroll
        for (int kk = 0; kk < 2; kk++) {
            const int kb = kk * 16 + tq * 2;
            uint32_t ah[4][4], al[4][4], bh[4][2], bl[4][2];
#pragma unroll
            for (int mt = 0; mt < 4; mt++) {
                const int r0 = wm * 64 + mt * 16 + g;
                ah[mt][0] = *(const uint32_t*)(Ah + r0 * TSTR + kb);
                ah[mt][1] = *(const uint32_t*)(Ah + (r0 + 8) * TSTR + kb);
                ah[mt][2] = *(const uint32_t*)(Ah + r0 * TSTR + kb + 8);
                ah[mt][3] = *(const uint32_t*)(Ah + (r0 + 8) * TSTR + kb + 8);
                al[mt][0] = *(const uint32_t*)(Al + r0 * TSTR + kb);
                al[mt][1] = *(const uint32_t*)(Al + (r0 + 8) * TSTR + kb);
                al[mt][2] = *(const uint32_t*)(Al + r0 * TSTR + kb + 8);
                al[mt][3] = *(const uint32_t*)(Al + (r0 + 8) * TSTR + kb + 8);
            }
#pragma unroll
            for (int nt = 0; nt < 4; nt++) {
                const int n0 = wn * 32 + nt * 8 + g;
                bh[nt][0] = *(const uint32_t*)(Bh + n0 * TSTR + kb);
                bh[nt][1] = *(const uint32_t*)(Bh + n0 * TSTR + kb + 8);
                bl[nt][0] = *(const uint32_t*)(Bl + n0 * TSTR + kb);
                bl[nt][1] = *(const uint32_t*)(Bl + n0 * TSTR + kb + 8);
            }
#pragma unroll
            for (int mt = 0; mt < 4; mt++)
#pragma unroll
                for (int nt = 0; nt < 4; nt++) {
                    mma16816(acc[mt][nt], ah[mt], bh[nt]);
                    mma16816(acc[mt][nt], ah[mt], bl[nt]);
                    mma16816(acc[mt][nt], al[mt], bh[nt]);
                }
        }
    };

    ldg_stage(0);
    sts_stage(0);
    __syncthreads();

    for (int s = 0; s < NS; s++) {
        if (s + 1 < NS) ldg_stage(s + 1);
        compute(s & 1);
        if (s + 1 < NS) sts_stage((s + 1) & 1);
        __syncthreads();
    }

#pragma unroll
    for (int mt = 0; mt < 4; mt++) {
        const int row = bm + wm * 64 + mt * 16 + g;
#pragma unroll
        for (int nt = 0; nt < 4; nt++) {
            const int col = bn + wn * 32 + nt * 8 + tq * 2;
            if (SPLIT_OUT) {
                uint32_t* Yh32 = (uint32_t*)Yh;
                uint32_t* Yl32 = (uint32_t*)Yl;
                float a, b;
                uint32_t h0 = packbf(acc[mt][nt][0], acc[mt][nt][1]);
                unpackbf(h0, a, b);
                uint32_t l0 = packbf(acc[mt][nt][0] - a, acc[mt][nt][1] - b);
                Yh32[((size_t)row * DDIM + col) >> 1] = h0;
                Yl32[((size_t)row * DDIM + col) >> 1] = l0;
                uint32_t h1 = packbf(acc[mt][nt][2], acc[mt][nt][3]);
                unpackbf(h1, a, b);
                uint32_t l1 = packbf(acc[mt][nt][2] - a, acc[mt][nt][3] - b);
                Yh32[((size_t)(row + 8) * DDIM + col) >> 1] = h1;
                Yl32[((size_t)(row + 8) * DDIM + col) >> 1] = l1;
            } else {
                *(float2*)(Yf + (size_t)row * DDIM + col) =
                    make_float2(acc[mt][nt][0], acc[mt][nt][1]);
                *(float2*)(Yf + (size_t)(row + 8) * DDIM + col) =
                    make_float2(acc[mt][nt][2], acc[mt][nt][3]);
            }
        }
    }
}

__global__ __launch_bounds__(256, 1) void qkv_mma(const float* __restrict__ X,
                                                  const float* __restrict__ Wq,
                                                  const float* __restrict__ Wk,
                                                  const float* __restrict__ Wv) {
    const float* W = (blockIdx.z == 0) ? Wq : (blockIdx.z == 1) ? Wk : Wv;
    __nv_bfloat16* Yh = (blockIdx.z == 0) ? g_Qh : (blockIdx.z == 1) ? g_Kh : g_Vh;
    __nv_bfloat16* Yl = (blockIdx.z == 0) ? g_Ql : (blockIdx.z == 1) ? g_Kl : g_Vl;
    mma_gemm<true>(X, W, nullptr, Yh, Yl);
}

__global__ __launch_bounds__(256, 1) void oproj_mma(const float* __restrict__ Wo,
                                                    float* __restrict__ out) {
    mma_gemm<false>(g_A, Wo, out, nullptr, nullptr);
}

// ===================== Flash attention (mma.sync bf16 split) =====================
// CTA: 128 q rows x one (b,h). 8 warps x 16 rows. kv tiles of 64, double buffered.
#define NT (SLEN / 64)        // 32 kv tiles
#define RSTR 144              // smem row stride bytes (72 bf16): conflict-free LDSM
#define KVARR (64 * RSTR)     // 9216 B per array
#define KVBUF (4 * KVARR)     // Kh,Kl,Vh,Vl
#define QARR (128 * RSTR)     // 18432 B
#define ATT_SMEM (2 * QARR + 2 * KVBUF)  // 110592 B

__global__ __launch_bounds__(256, 1) void attn_mma() {
    extern __shared__ char smem_raw[];
    const uint32_t smb = smem_u32(smem_raw);
    const uint32_t q_u32 = smb;
    const uint32_t kv_u32 = smb + 2 * QARR;

    const int tid = threadIdx.x;
    const int wm = tid >> 5;       // warp 0..7 -> rows wm*16
    const int lane = tid & 31;
    const int g = lane >> 2;
    const int tq = lane & 3;
    const int mi = lane >> 3;      // ldmatrix matrix index 0..3
    const int r8 = lane & 7;       // ldmatrix row within matrix
    const int b = blockIdx.y >> 4;
    const int h = blockIdx.y & 15;
    const int q0 = blockIdx.x * 128;
    const size_t bS = (size_t)b * SLEN;
    const int hoff = h * DKH;

    // ---- issue Q loads (group 0) ----
    {
        int arr = tid >> 7, row = tid & 127;
        const __nv_bfloat16* gp =
            (arr ? g_Ql : g_Qh) + (bS + q0 + row) * DDIM + hoff;
        uint32_t dst = q_u32 + arr * QARR + row * RSTR;
#pragma unroll
        for (int i = 0; i < 8; i++) CP16(dst + i * 16, gp + i * 8);
    }
    CP_COMMIT();

    // ---- kv tile loader ----
    auto load_kv = [&](int t, int bb) {
        int arr = tid >> 6, row = tid & 63;
        const __nv_bfloat16* gp =
            (arr == 0 ? g_Kh : arr == 1 ? g_Kl : arr == 2 ? g_Vh : g_Vl) +
            (bS + t * 64 + row) * DDIM + hoff;
        uint32_t dst = kv_u32 + bb * KVBUF + arr * KVARR + row * RSTR;
#pragma unroll
        for (int i = 0; i < 8; i++) CP16(dst + i * 16, gp + i * 8);
    };

    load_kv(0, 0);
    CP_COMMIT();  // group 1

    // state
    float s[8][4];
    float o[8][4];
    float ms0 = -1e30f, ms1 = -1e30f, l0 = 0.f, l1 = 0.f;
#pragma unroll
    for (int j = 0; j < 8; j++)
#pragma unroll
        for (int c = 0; c < 4; c++) o[j][c] = 0.f;
    const float SCL = 0.125f * 1.4426950408889634f;

    // ---- Q fragments (hi/lo), kept in registers ----
    CP_WAIT(1);  // Q group done
    __syncthreads();
    uint32_t ah[4][4], al[4][4];
#pragma unroll
    for (int kt = 0; kt < 4; kt++) {
        uint32_t addr = q_u32 + (wm * 16 + (mi & 1) * 8 + r8) * RSTR +
                        (kt * 16 + (mi >> 1) * 8) * 2;
        LDSM4(ah[kt][0], ah[kt][1], ah[kt][2], ah[kt][3], addr);
        LDSM4(al[kt][0], al[kt][1], al[kt][2], al[kt][3], addr + QARR);
    }

    for (int t = 0; t < NT; t++) {
        if (t + 1 < NT) {
            load_kv(t + 1, (t + 1) & 1);
            CP_COMMIT();
            CP_WAIT(1);
        } else {
            CP_WAIT(0);
        }
        __syncthreads();

        const uint32_t khb = kv_u32 + (t & 1) * KVBUF;
        const uint32_t vhb = khb + 2 * KVARR;

        // ---- S = Q K^T (3-term split) ----
#pragma unroll
        for (int j = 0; j < 8; j++)
#pragma unroll
            for (int c = 0; c < 4; c++) s[j][c] = 0.f;
#pragma unroll
        for (int kt = 0; kt < 4; kt++) {
#pragma unroll
            for (int j2 = 0; j2 < 4; j2++) {
                uint32_t addr = khb + (16 * j2 + (mi >> 1) * 8 + r8) * RSTR +
                                (kt * 16 + (mi & 1) * 8) * 2;
                uint32_t bh[4], bl[4];
                LDSM4(bh[0], bh[1], bh[2], bh[3], addr);
                LDSM4(bl[0], bl[1], bl[2], bl[3], addr + KVARR);
                mma16816(s[2 * j2], ah[kt], bh);
                mma16816(s[2 * j2], ah[kt], bl);
                mma16816(s[2 * j2], al[kt], bh);
                mma16816(s[2 * j2 + 1], ah[kt], bh + 2);
                mma16816(s[2 * j2 + 1], ah[kt], bl + 2);
                mma16816(s[2 * j2 + 1], al[kt], bh + 2);
            }
        }

        // ---- online softmax (fexp2 on fma pipe) ----
        float mx0 = -1e30f, mx1 = -1e30f;
#pragma unroll
        for (int j = 0; j < 8; j++) {
            mx0 = fmaxf(mx0, fmaxf(s[j][0], s[j][1]));
            mx1 = fmaxf(mx1, fmaxf(s[j][2], s[j][3]));
        }
        mx0 = fmaxf(mx0, __shfl_xor_sync(0xffffffffu, mx0, 1));
        mx0 = fmaxf(mx0, __shfl_xor_sync(0xffffffffu, mx0, 2));
        mx1 = fmaxf(mx1, __shfl_xor_sync(0xffffffffu, mx1, 1));
        mx1 = fmaxf(mx1, __shfl_xor_sync(0xffffffffu, mx1, 2));
        float ns0 = fmaxf(ms0, mx0 * SCL);
        float ns1 = fmaxf(ms1, mx1 * SCL);
        float al0 = fexp2(ms0 - ns0);
        float al1 = fexp2(ms1 - ns1);
        ms0 = ns0;
        ms1 = ns1;
        float rs0 = 0.f, rs1 = 0.f;
#pragma unroll
        for (int j = 0; j < 8; j++) {
            float p0 = fexp2(fmaf(s[j][0], SCL, -ns0));
            float p1 = fexp2(fmaf(s[j][1], SCL, -ns0));
            float p2 = fexp2(fmaf(s[j][2], SCL, -ns1));
            float p3 = fexp2(fmaf(s[j][3], SCL, -ns1));
            s[j][0] = p0; s[j][1] = p1; s[j][2] = p2; s[j][3] = p3;
            rs0 += p0 + p1;
            rs1 += p2 + p3;
        }
        rs0 += __shfl_xor_sync(0xffffffffu, rs0, 1);
        rs0 += __shfl_xor_sync(0xffffffffu, rs0, 2);
        rs1 += __shfl_xor_sync(0xffffffffu, rs1, 1);
        rs1 += __shfl_xor_sync(0xffffffffu, rs1, 2);
        l0 = l0 * al0 + rs0;
        l1 = l1 * al1 + rs1;
#pragma unroll
        for (int j = 0; j < 8; j++) {
            o[j][0] *= al0; o[j][1] *= al0;
            o[j][2] *= al1; o[j][3] *= al1;
        }

        // ---- O += P V (3-term split; P frags from S registers) ----
#pragma unroll
        for (int kt = 0; kt < 4; kt++) {
            uint32_t aph[4], apl[4];
#pragma unroll
            for (int u = 0; u < 2; u++) {
                const int j = 2 * kt + u;
                uint32_t h0 = packbf(s[j][0], s[j][1]);
                uint32_t h1 = packbf(s[j][2], s[j][3]);
                float a, bb, c, d;
                unpackbf(h0, a, bb);
                unpackbf(h1, c, d);
                aph[2 * u] = h0;
                aph[2 * u + 1] = h1;
                apl[2 * u] = packbf(s[j][0] - a, s[j][1] - bb);
                apl[2 * u + 1] = packbf(s[j][2] - c, s[j][3] - d);
            }
            // reorder: a frag = {a0,a1,a2,a3} = {t2k row pair, t2k+1 row pair}
            uint32_t APH[4] = {aph[0], aph[1], aph[2], aph[3]};
            uint32_t APL[4] = {apl[0], apl[1], apl[2], apl[3]};
#pragma unroll
            for (int j2 = 0; j2 < 4; j2++) {
                uint32_t addr = vhb + (kt * 16 + (mi & 1) * 8 + r8) * RSTR +
                                (16 * j2 + (mi >> 1) * 8) * 2;
                uint32_t bh[4], bl[4];
                LDSM4T(bh[0], bh[1], bh[2], bh[3], addr);
                LDSM4T(bl[0], bl[1], bl[2], bl[3], addr + KVARR);
                mma16816(o[2 * j2], APH, bh);
                mma16816(o[2 * j2], APH, bl);
                mma16816(o[2 * j2], APL, bh);
                mma16816(o[2 * j2 + 1], APH, bh + 2);
                mma16816(o[2 * j2 + 1], APH, bl + 2);
                mma16816(o[2 * j2 + 1], APL, bh + 2);
            }
        }
        __syncthreads();
    }

    // ---- epilogue: normalize, write fp32 to g_A ----
    const float inv0 = 1.f / l0;
    const float inv1 = 1.f / l1;
    const int row0 = q0 + wm * 16 + g;
#pragma unroll
    for (int j = 0; j < 8; j++) {
        const int col = hoff + j * 8 + tq * 2;
        *(float2*)(g_A + (bS + row0) * DDIM + col) =
            make_float2(o[j][0] * inv0, o[j][1] * inv0);
        *(float2*)(g_A + (bS + row0 + 8) * DDIM + col) =
            make_float2(o[j][2] * inv1, o[j][3] * inv1);
    }
}

// ======================= launch =======================
extern "C" void kernel_launch(void* const* d_in, const int* in_sizes, int n_in,
                              void* d_out, int out_size) {
    const float* emb = (const float*)d_in[0];
    const float* Wq  = (const float*)d_in[1];
    const float* Wk  = (const float*)d_in[2];
    const float* Wv  = (const float*)d_in[3];
    const float* Wo  = (const float*)d_in[4];
    float* out = (float*)d_out;

    cudaFuncSetAttribute(qkv_mma, cudaFuncAttributeMaxDynamicSharedMemorySize, GEMM_SMEM);
    cudaFuncSetAttribute(oproj_mma, cudaFuncAttributeMaxDynamicSharedMemorySize, GEMM_SMEM);
    cudaFuncSetAttribute(attn_mma, cudaFuncAttributeMaxDynamicSharedMemorySize, ATT_SMEM);

    dim3 ggrid(DDIM / 128, MROWS / 128, 3);
    qkv_mma<<<ggrid, 256, GEMM_SMEM>>>(emb, Wq, Wk, Wv);

    dim3 agrid(SLEN / 128, BATCH * NHEAD);
    attn_mma<<<agrid, 256, ATT_SMEM>>>();

    dim3 ogrid(DDIM / 128, MROWS / 128, 1);
    oproj_mma<<<ogrid, 256, GEMM_SMEM>>>(Wo, out);
}